// round 1
// baseline (speedup 1.0000x reference)
#include <cuda_runtime.h>
#include <cstdint>

// Problem constants
#define BATCH 2
#define SEQ   2048
#define DIM   1024
#define NH    16
#define HD    64
#define MROWS (BATCH * SEQ)   // 4096

// Scratch (allocation-free rule: __device__ globals)
__device__ float g_Q[BATCH * NH * SEQ * HD];   // [b,h,s,hd]
__device__ float g_K[BATCH * NH * SEQ * HD];
__device__ float g_V[BATCH * NH * SEQ * HD];
__device__ float g_A[BATCH * SEQ * DIM];       // attention out, [b,s,h*hd]

// ---------------------------------------------------------------------------
// GEMM: C[m,n] = sum_k A[m,k] * W[n,k] + bias[n]
// M=4096, N=1024, K=1024. BM=BN=128, BK=16, 256 threads, 8x8 per thread.
// SPLIT_HEADS=1: write to [b,h,s,hd] layout; =0: plain row-major [m,n].
// ---------------------------------------------------------------------------
template <int SPLIT_HEADS>
__global__ __launch_bounds__(256) void gemm_bias(const float* __restrict__ A,
                                                 const float* __restrict__ W,
                                                 const float* __restrict__ bias,
                                                 float* __restrict__ C) {
    const int BM = 128, BN = 128, BK = 16;
    __shared__ float As[BK][BM + 4];   // +4 keeps rows 16B-aligned
    __shared__ float Ws[BK][BN + 4];

    const int m0 = blockIdx.y * BM;
    const int n0 = blockIdx.x * BN;
    const int tid = threadIdx.x;
    const int tm = tid >> 4;    // 0..15
    const int tn = tid & 15;    // 0..15

    float acc[8][8];
#pragma unroll
    for (int i = 0; i < 8; i++)
#pragma unroll
        for (int j = 0; j < 8; j++) acc[i][j] = 0.f;

    for (int k0 = 0; k0 < DIM; k0 += BK) {
#pragma unroll
        for (int it = 0; it < 2; it++) {
            int idx = tid + it * 256;          // 0..511
            int row = idx >> 2;                // 0..127
            int kc = (idx & 3) * 4;            // 0,4,8,12
            float4 va = *(const float4*)&A[(size_t)(m0 + row) * DIM + k0 + kc];
            As[kc + 0][row] = va.x;
            As[kc + 1][row] = va.y;
            As[kc + 2][row] = va.z;
            As[kc + 3][row] = va.w;
            float4 vw = *(const float4*)&W[(size_t)(n0 + row) * DIM + k0 + kc];
            Ws[kc + 0][row] = vw.x;
            Ws[kc + 1][row] = vw.y;
            Ws[kc + 2][row] = vw.z;
            Ws[kc + 3][row] = vw.w;
        }
        __syncthreads();

#pragma unroll
        for (int kk = 0; kk < BK; kk++) {
            float4 a0 = *(const float4*)&As[kk][tm * 4];
            float4 a1 = *(const float4*)&As[kk][64 + tm * 4];
            float4 w0 = *(const float4*)&Ws[kk][tn * 4];
            float4 w1 = *(const float4*)&Ws[kk][64 + tn * 4];
            float a[8] = {a0.x, a0.y, a0.z, a0.w, a1.x, a1.y, a1.z, a1.w};
            float w[8] = {w0.x, w0.y, w0.z, w0.w, w1.x, w1.y, w1.z, w1.w};
#pragma unroll
            for (int i = 0; i < 8; i++)
#pragma unroll
                for (int j = 0; j < 8; j++) acc[i][j] += a[i] * w[j];
        }
        __syncthreads();
    }

    // Bias values for this thread's 8 columns (two groups of 4)
    float bv[8];
#pragma unroll
    for (int j = 0; j < 4; j++) {
        bv[j]     = bias[n0 + tn * 4 + j];
        bv[4 + j] = bias[n0 + 64 + tn * 4 + j];
    }

#pragma unroll
    for (int ig = 0; ig < 2; ig++) {
#pragma unroll
        for (int ii = 0; ii < 4; ii++) {
            int i = ig * 4 + ii;
            int m = m0 + ig * 64 + tm * 4 + ii;
#pragma unroll
            for (int jg = 0; jg < 2; jg++) {
                int n = n0 + jg * 64 + tn * 4;
                float4 r;
                r.x = acc[i][jg * 4 + 0] + bv[jg * 4 + 0];
                r.y = acc[i][jg * 4 + 1] + bv[jg * 4 + 1];
                r.z = acc[i][jg * 4 + 2] + bv[jg * 4 + 2];
                r.w = acc[i][jg * 4 + 3] + bv[jg * 4 + 3];
                if (SPLIT_HEADS) {
                    int b = m >> 11;          // m / SEQ
                    int s = m & (SEQ - 1);
                    int h = n >> 6;           // n / HD
                    int hd = n & (HD - 1);
                    float* dst = &C[((size_t)((b * NH + h) * SEQ + s)) * HD + hd];
                    *(float4*)dst = r;
                } else {
                    *(float4*)&C[(size_t)m * DIM + n] = r;
                }
            }
        }
    }
}

// ---------------------------------------------------------------------------
// Flash attention, fp32 SIMT. One thread = one query row (Hd=64 in regs).
// Block = 128 threads = 128 query rows of one (b,h). K/V tiled 64 rows in smem
// (broadcast reads: all lanes in a warp read the same K/V row -> conflict-free).
// ---------------------------------------------------------------------------
__global__ __launch_bounds__(128) void flash_attn(const int* __restrict__ mask,
                                                  float* __restrict__ Out) {
    const int b = blockIdx.z;
    const int h = blockIdx.y;
    const int tid = threadIdx.x;
    const int qrow = blockIdx.x * 128 + tid;

    const float* Qp = g_Q + ((size_t)((b * NH + h) * SEQ) + qrow) * HD;
    const float* Kb = g_K + ((size_t)((b * NH + h) * SEQ)) * HD;
    const float* Vb = g_V + ((size_t)((b * NH + h) * SEQ)) * HD;

    float q[HD];
#pragma unroll
    for (int i = 0; i < HD / 4; i++) {
        float4 v = *(const float4*)&Qp[i * 4];
        q[i * 4 + 0] = v.x; q[i * 4 + 1] = v.y; q[i * 4 + 2] = v.z; q[i * 4 + 3] = v.w;
    }

    float o[HD];
#pragma unroll
    for (int d = 0; d < HD; d++) o[d] = 0.f;
    float mx = -1e30f;
    float l = 0.f;
    const float scale = 0.125f;   // 1/sqrt(64)

    __shared__ float Ks[64 * HD];
    __shared__ float Vs[64 * HD];
    __shared__ int msk[64];

    for (int kt = 0; kt < SEQ / 64; kt++) {
        __syncthreads();
#pragma unroll
        for (int it = 0; it < 8; it++) {
            int idx = tid + it * 128;           // 0..1023 (float4 index)
            int row = idx >> 4;                 // 0..63
            int c = (idx & 15) * 4;             // 0..60
            *(float4*)&Ks[row * HD + c] = *(const float4*)&Kb[((size_t)(kt * 64 + row)) * HD + c];
            *(float4*)&Vs[row * HD + c] = *(const float4*)&Vb[((size_t)(kt * 64 + row)) * HD + c];
        }
        if (tid < 64) msk[tid] = mask[b * SEQ + kt * 64 + tid];
        __syncthreads();

#pragma unroll 1
        for (int j = 0; j < 64; j++) {
            float s = 0.f;
            const float4* kr = (const float4*)&Ks[j * HD];
#pragma unroll
            for (int d4 = 0; d4 < HD / 4; d4++) {
                float4 kv = kr[d4];
                s += q[d4 * 4 + 0] * kv.x;
                s += q[d4 * 4 + 1] * kv.y;
                s += q[d4 * 4 + 2] * kv.z;
                s += q[d4 * 4 + 3] * kv.w;
            }
            s *= scale;
            if (msk[j]) s = -1e38f;

            float p;
            if (s > mx) {
                float corr = __expf(mx - s);
                l *= corr;
#pragma unroll
                for (int d = 0; d < HD; d++) o[d] *= corr;
                mx = s;
                p = 1.f;
            } else {
                p = __expf(s - mx);
            }
            l += p;

            const float4* vr = (const float4*)&Vs[j * HD];
#pragma unroll
            for (int d4 = 0; d4 < HD / 4; d4++) {
                float4 vv = vr[d4];
                o[d4 * 4 + 0] += p * vv.x;
                o[d4 * 4 + 1] += p * vv.y;
                o[d4 * 4 + 2] += p * vv.z;
                o[d4 * 4 + 3] += p * vv.w;
            }
        }
    }

    float inv = 1.f / l;
    float* Op = Out + ((size_t)(b * SEQ + qrow)) * DIM + h * HD;
#pragma unroll
    for (int i = 0; i < HD / 4; i++) {
        float4 v;
        v.x = o[i * 4 + 0] * inv;
        v.y = o[i * 4 + 1] * inv;
        v.z = o[i * 4 + 2] * inv;
        v.w = o[i * 4 + 3] * inv;
        *(float4*)&Op[i * 4] = v;
    }
}

// ---------------------------------------------------------------------------
extern "C" void kernel_launch(void* const* d_in, const int* in_sizes, int n_in,
                              void* d_out, int out_size) {
    const float* q  = (const float*)d_in[0];
    const float* k  = (const float*)d_in[1];
    const float* v  = (const float*)d_in[2];
    const int* mask = (const int*)d_in[3];
    const float* Wq = (const float*)d_in[4];
    const float* bq = (const float*)d_in[5];
    const float* Wk = (const float*)d_in[6];
    const float* bk = (const float*)d_in[7];
    const float* Wv = (const float*)d_in[8];
    const float* bv = (const float*)d_in[9];
    const float* Wo = (const float*)d_in[10];
    const float* bo = (const float*)d_in[11];
    float* out = (float*)d_out;

    float *pQ, *pK, *pV, *pA;
    cudaGetSymbolAddress((void**)&pQ, g_Q);
    cudaGetSymbolAddress((void**)&pK, g_K);
    cudaGetSymbolAddress((void**)&pV, g_V);
    cudaGetSymbolAddress((void**)&pA, g_A);

    dim3 gg(DIM / 128, MROWS / 128);   // (8, 32)
    gemm_bias<1><<<gg, 256>>>(q, Wq, bq, pQ);
    gemm_bias<1><<<gg, 256>>>(k, Wk, bk, pK);
    gemm_bias<1><<<gg, 256>>>(v, Wv, bv, pV);

    flash_attn<<<dim3(SEQ / 128, NH, BATCH), 128>>>(mask, pA);

    gemm_bias<0><<<gg, 256>>>(pA, Wo, bo, out);
}